// round 4
// baseline (speedup 1.0000x reference)
#include <cuda_runtime.h>
#include <math.h>

#define BB   512
#define FREQ 8
#define EE   1024
#define HH   8
#define HD   128
#define DIN  3072
#define LROWS 4096
#define SEQ  512
#define NH   64

// scratch
__device__ float g_z[LROWS * EE];
__device__ float g_qkv[LROWS * 3 * EE];
__device__ float g_scores[NH * SEQ * SEQ];
__device__ float g_attn_o[LROWS * EE];
__device__ float g_zrec[LROWS * EE];
// pre-rounded tf32 copies
__device__ float g_xtf[LROWS * DIN];
__device__ float g_encW[DIN * EE];
__device__ float g_inprojW[3 * EE * EE];
__device__ float g_outW[EE * EE];
__device__ float g_decW[EE * DIN];

#define AS 24            // A smem row stride (16 k + 8 pad words) -> conflict-free LDS.64
#define BS_TB 24         // B(NT) same layout as A
#define BS_NN 132        // B(NN) [k][n] row stride words (128 + 4 pad)
#define NSTAGE 3

__device__ __forceinline__ unsigned f2tf(float f) {
    unsigned u;
    asm("cvt.rna.tf32.f32 %0, %1;" : "=r"(u) : "f"(f));
    return u;
}
__device__ __forceinline__ float roundtf(float f) { return __uint_as_float(f2tf(f)); }

__device__ __forceinline__ unsigned smem_u32(const void* p) {
    unsigned a;
    asm("{ .reg .u64 t; cvta.to.shared.u64 t, %1; cvt.u32.u64 %0, t; }"
        : "=r"(a) : "l"(p));
    return a;
}
__device__ __forceinline__ void cp16(unsigned dst, const void* src) {
    asm volatile("cp.async.cg.shared.global [%0], [%1], 16;" :: "r"(dst), "l"(src));
}
__device__ __forceinline__ void mma_tf32(float c[4], const unsigned a[4], const unsigned b[2]) {
    asm volatile(
        "mma.sync.aligned.m16n8k8.row.col.f32.tf32.tf32.f32 "
        "{%0,%1,%2,%3}, {%4,%5,%6,%7}, {%8,%9}, {%0,%1,%2,%3};\n"
        : "+f"(c[0]), "+f"(c[1]), "+f"(c[2]), "+f"(c[3])
        : "r"(a[0]), "r"(a[1]), "r"(a[2]), "r"(a[3]), "r"(b[0]), "r"(b[1]));
}

// C = alpha * A @ (TB ? B^T : B) + bias, batched/strided. Inputs pre-rounded to tf32.
// 128x128 CTA tile, K-step 16, 8 warps of 64x32, 3-stage cp.async pipeline.
template<bool TB, bool ROUND>
__global__ __launch_bounds__(256)
void gemm_tc(const float* __restrict__ A, long long lda, long long sA1, long long sA2,
             const float* __restrict__ Bm, long long ldb, long long sB1, long long sB2,
             const float* __restrict__ bias,
             float* __restrict__ C, long long ldc, long long sC1, long long sC2,
             int K, float alpha, int bdiv)
{
    constexpr int ABUF = 128 * AS;                       // words per stage
    constexpr int BBUF = TB ? (128 * BS_TB) : (16 * BS_NN);
    extern __shared__ float smem[];
    float* Asm = smem;                                   // NSTAGE * ABUF
    float* Bsm = smem + NSTAGE * ABUF;                   // NSTAGE * BBUF

    const int bz = blockIdx.z;
    const int n_b = bz / bdiv, h_b = bz % bdiv;
    A  += n_b * sA1 + h_b * sA2;
    Bm += n_b * sB1 + h_b * sB2;
    C  += n_b * sC1 + h_b * sC2;

    const int rowBase = blockIdx.y * 128;
    const int colBase = blockIdx.x * 128;
    const int tid  = threadIdx.x;
    const int wid  = tid >> 5;
    const int lane = tid & 31;
    const int warpM = wid >> 2;      // 0..1
    const int warpN = wid & 3;       // 0..3
    const int gid = lane >> 2;       // 0..7
    const int tig = lane & 3;        // 0..3

    // ---- per-thread copy slots ----
    const int arow = tid >> 1;
    const int ak4  = (tid & 1) * 8;
    const float* aSrc = A + (long long)(rowBase + arow) * lda + ak4;
    const unsigned aDst0 = smem_u32(&Asm[arow * AS + ak4]);

    const float* bSrc;
    unsigned bDst0;
    long long bStep2 = 0;
    if (TB) {
        bSrc = Bm + (long long)(colBase + arow) * ldb + ak4;
        bDst0 = smem_u32(&Bsm[arow * BS_TB + ak4]);
    } else {
        const int bkr = tid >> 5;
        const int bn4 = (tid & 31) * 4;
        bSrc = Bm + (long long)bkr * ldb + colBase + bn4;
        bStep2 = 8LL * ldb;
        bDst0 = smem_u32(&Bsm[bkr * BS_NN + bn4]);
    }

    const int KT = K >> 4;

    // issue copy for tile kt into stage kt%3
    auto issue = [&](int kt) {
        const int st = kt % NSTAGE;
        const unsigned ad = aDst0 + st * (ABUF * 4);
        const unsigned bd = bDst0 + st * (BBUF * 4);
        const int k0 = kt << 4;
        cp16(ad,      aSrc + k0);
        cp16(ad + 16, aSrc + k0 + 4);
        if (TB) {
            cp16(bd,      bSrc + k0);
            cp16(bd + 16, bSrc + k0 + 4);
        } else {
            const float* bs = bSrc + (long long)k0 * ldb;
            cp16(bd, bs);
            cp16(bd + 8 * BS_NN * 4, bs + bStep2);
        }
        asm volatile("cp.async.commit_group;" ::: "memory");
    };

    float acc[4][4][4];
#pragma unroll
    for (int i = 0; i < 4; i++)
#pragma unroll
        for (int j = 0; j < 4; j++)
#pragma unroll
            for (int r = 0; r < 4; r++) acc[i][j][r] = 0.0f;

    issue(0);
    issue(1);

    for (int kt = 0; kt < KT; kt++) {
        if (kt + 1 < KT) asm volatile("cp.async.wait_group 1;" ::: "memory");
        else             asm volatile("cp.async.wait_group 0;" ::: "memory");
        __syncthreads();
        if (kt + 2 < KT) issue(kt + 2);

        const float* as = Asm + (kt % NSTAGE) * ABUF;
        const float* bs = Bsm + (kt % NSTAGE) * BBUF;

#pragma unroll
        for (int ks = 0; ks < 16; ks += 8) {
            // phys-k pairing: thread tig owns physical k = ks+2*tig, ks+2*tig+1
            unsigned afr[4][4];
#pragma unroll
            for (int mt = 0; mt < 4; mt++) {
                const int r = warpM * 64 + mt * 16 + gid;
                const float2 v0 = *(const float2*)&as[r * AS + ks + 2 * tig];
                const float2 v1 = *(const float2*)&as[(r + 8) * AS + ks + 2 * tig];
                afr[mt][0] = __float_as_uint(v0.x);
                afr[mt][1] = __float_as_uint(v1.x);
                afr[mt][2] = __float_as_uint(v0.y);
                afr[mt][3] = __float_as_uint(v1.y);
            }
            unsigned bfr[4][2];
#pragma unroll
            for (int nt = 0; nt < 4; nt++) {
                const int n = warpN * 32 + nt * 8 + gid;
                if (TB) {
                    const float2 w = *(const float2*)&bs[n * BS_TB + ks + 2 * tig];
                    bfr[nt][0] = __float_as_uint(w.x);
                    bfr[nt][1] = __float_as_uint(w.y);
                } else {
                    bfr[nt][0] = __float_as_uint(bs[(ks + 2 * tig) * BS_NN + n]);
                    bfr[nt][1] = __float_as_uint(bs[(ks + 2 * tig + 1) * BS_NN + n]);
                }
            }
#pragma unroll
            for (int mt = 0; mt < 4; mt++)
#pragma unroll
                for (int nt = 0; nt < 4; nt++)
                    mma_tf32(acc[mt][nt], afr[mt], bfr[nt]);
        }
    }

    // epilogue
#pragma unroll
    for (int mt = 0; mt < 4; mt++) {
        const int r0 = rowBase + warpM * 64 + mt * 16 + gid;
#pragma unroll
        for (int nt = 0; nt < 4; nt++) {
            const int c0 = colBase + warpN * 32 + nt * 8 + tig * 2;
            float b0 = 0.0f, b1 = 0.0f;
            if (bias) { b0 = bias[c0]; b1 = bias[c0 + 1]; }
            float2 v0, v1;
            v0.x = acc[mt][nt][0] * alpha + b0;
            v0.y = acc[mt][nt][1] * alpha + b1;
            v1.x = acc[mt][nt][2] * alpha + b0;
            v1.y = acc[mt][nt][3] * alpha + b1;
            if (ROUND) {
                v0.x = roundtf(v0.x); v0.y = roundtf(v0.y);
                v1.x = roundtf(v1.x); v1.y = roundtf(v1.y);
            }
            *(float2*)(C + (long long)r0 * ldc + c0) = v0;
            *(float2*)(C + (long long)(r0 + 8) * ldc + c0) = v1;
        }
    }
}

__global__ __launch_bounds__(256)
void round_tf32_kernel(const float4* __restrict__ in, float4* __restrict__ out, int n4)
{
    const int i = blockIdx.x * blockDim.x + threadIdx.x;
    if (i < n4) {
        float4 v = in[i];
        v.x = roundtf(v.x); v.y = roundtf(v.y);
        v.z = roundtf(v.z); v.w = roundtf(v.w);
        out[i] = v;
    }
}

__global__ __launch_bounds__(256)
void softmax512(float* __restrict__ S)
{
    float* p = S + (long long)blockIdx.x * 512;
    const int t = threadIdx.x;
    const float a = p[t];
    const float b = p[t + 256];

    float m = fmaxf(a, b);
#pragma unroll
    for (int o = 16; o; o >>= 1) m = fmaxf(m, __shfl_xor_sync(0xFFFFFFFFu, m, o));
    __shared__ float sm[8];
    if ((t & 31) == 0) sm[t >> 5] = m;
    __syncthreads();
    float mm = sm[0];
#pragma unroll
    for (int i = 1; i < 8; i++) mm = fmaxf(mm, sm[i]);

    const float e0 = __expf(a - mm);
    const float e1 = __expf(b - mm);
    float s = e0 + e1;
#pragma unroll
    for (int o = 16; o; o >>= 1) s += __shfl_xor_sync(0xFFFFFFFFu, s, o);
    __shared__ float ss[8];
    if ((t & 31) == 0) ss[t >> 5] = s;
    __syncthreads();
    float tot = 0.0f;
#pragma unroll
    for (int i = 0; i < 8; i++) tot += ss[i];
    const float inv = 1.0f / tot;
    // pre-round P to tf32 (it is the A-operand of the PV GEMM)
    p[t]       = roundtf(e0 * inv);
    p[t + 256] = roundtf(e1 * inv);
}

__global__ __launch_bounds__(256)
void pred_kernel(const float* __restrict__ xrec, float* __restrict__ xpred)
{
    const int idx = blockIdx.x * blockDim.x + threadIdx.x;
    const int c4 = idx & 15;
    const int t  = (idx >> 4) % 192;
    const int b  = idx / (16 * 192);
    const int s  = t % 48;
    const float4 v = *(const float4*)(xrec + (long long)b * 24576 + 7 * 3072 + s * 64 + c4 * 4);
    ((float4*)xpred)[idx] = v;
}

extern "C" void kernel_launch(void* const* d_in, const int* in_sizes, int n_in,
                              void* d_out, int out_size)
{
    const float* x        = (const float*)d_in[0];
    const float* enc_W    = (const float*)d_in[1];
    const float* enc_b    = (const float*)d_in[2];
    const float* dec_W    = (const float*)d_in[3];
    const float* dec_b    = (const float*)d_in[4];
    const float* in_projW = (const float*)d_in[5];
    const float* in_projb = (const float*)d_in[6];
    const float* out_W    = (const float*)d_in[7];
    const float* out_b    = (const float*)d_in[8];
    float* out = (float*)d_out;

    float *z, *qkv, *scores, *attn_o, *zrec;
    float *xtf, *encW, *inprojW, *outW, *decW;
    cudaGetSymbolAddress((void**)&z,      g_z);
    cudaGetSymbolAddress((void**)&qkv,    g_qkv);
    cudaGetSymbolAddress((void**)&scores, g_scores);
    cudaGetSymbolAddress((void**)&attn_o, g_attn_o);
    cudaGetSymbolAddress((void**)&zrec,   g_zrec);
    cudaGetSymbolAddress((void**)&xtf,     g_xtf);
    cudaGetSymbolAddress((void**)&encW,    g_encW);
    cudaGetSymbolAddress((void**)&inprojW, g_inprojW);
    cudaGetSymbolAddress((void**)&outW,    g_outW);
    cudaGetSymbolAddress((void**)&decW,    g_decW);

    // dynamic smem sizes (bytes)
    const int SM_TB = NSTAGE * (128 * AS + 128 * BS_TB) * 4;   // 73728
    const int SM_NN = NSTAGE * (128 * AS + 16 * BS_NN) * 4;    // 62208
    cudaFuncSetAttribute(gemm_tc<false, true>,  cudaFuncAttributeMaxDynamicSharedMemorySize, SM_NN);
    cudaFuncSetAttribute(gemm_tc<false, false>, cudaFuncAttributeMaxDynamicSharedMemorySize, SM_NN);
    cudaFuncSetAttribute(gemm_tc<true, true>,   cudaFuncAttributeMaxDynamicSharedMemorySize, SM_TB);
    cudaFuncSetAttribute(gemm_tc<true, false>,  cudaFuncAttributeMaxDynamicSharedMemorySize, SM_TB);

    const float att_scale = 1.0f / sqrtf((float)HD);
    const long long QKV_L = 3LL * EE;
    const long long LDQKV = 3LL * EE * FREQ;

    // 0) pre-round inputs to tf32
    round_tf32_kernel<<<(LROWS * DIN / 4 + 255) / 256, 256>>>((const float4*)x, (float4*)xtf, LROWS * DIN / 4);
    round_tf32_kernel<<<(DIN * EE / 4 + 255) / 256, 256>>>((const float4*)enc_W, (float4*)encW, DIN * EE / 4);
    round_tf32_kernel<<<(3 * EE * EE / 4 + 255) / 256, 256>>>((const float4*)in_projW, (float4*)inprojW, 3 * EE * EE / 4);
    round_tf32_kernel<<<(EE * EE / 4 + 255) / 256, 256>>>((const float4*)out_W, (float4*)outW, EE * EE / 4);
    round_tf32_kernel<<<(EE * DIN / 4 + 255) / 256, 256>>>((const float4*)dec_W, (float4*)decW, EE * DIN / 4);

    // 1) z = x @ enc_W + enc_b                       (NN, 4096x1024x3072)
    gemm_tc<false, true><<<dim3(EE / 128, LROWS / 128, 1), 256, SM_NN>>>(
        xtf, DIN, 0, 0, encW, EE, 0, 0, enc_b,
        z, EE, 0, 0, DIN, 1.0f, 1);

    // 2) qkv = z @ in_proj_W^T + in_proj_b           (NT, 4096x3072x1024)
    gemm_tc<true, true><<<dim3(3 * EE / 128, LROWS / 128, 1), 256, SM_TB>>>(
        z, EE, 0, 0, inprojW, EE, 0, 0, in_projb,
        qkv, 3 * EE, 0, 0, EE, 1.0f, 1);

    // 3) scores = alpha * Q @ K^T                    (NT batched, 64 x 512x512x128)
    gemm_tc<true, false><<<dim3(SEQ / 128, SEQ / 128, NH), 256, SM_TB>>>(
        qkv,      LDQKV, QKV_L, HD,
        qkv + EE, LDQKV, QKV_L, HD,
        nullptr,
        scores, SEQ, (long long)HH * SEQ * SEQ, (long long)SEQ * SEQ,
        HD, att_scale, HH);

    // 4) softmax (+ tf32 round of P)
    softmax512<<<NH * SEQ, 256>>>(scores);

    // 5) attn_o = P @ V into (L,N,E) layout          (NN batched, 64 x 512x128x512)
    gemm_tc<false, true><<<dim3(HD / 128, SEQ / 128, NH), 256, SM_NN>>>(
        scores, SEQ, (long long)HH * SEQ * SEQ, (long long)SEQ * SEQ,
        qkv + 2 * EE, LDQKV, QKV_L, HD,
        nullptr,
        attn_o, (long long)FREQ * EE, EE, HD,
        SEQ, 1.0f, HH);

    // 6) z_rec = attn_o @ out_W^T + out_b            (NT, 4096x1024x1024)
    gemm_tc<true, true><<<dim3(EE / 128, LROWS / 128, 1), 256, SM_TB>>>(
        attn_o, EE, 0, 0, outW, EE, 0, 0, out_b,
        zrec, EE, 0, 0, EE, 1.0f, 1);

    // 7) x_rec = z_rec @ dec_W + dec_b -> d_out      (NN, 4096x3072x1024, fp32 out)
    gemm_tc<false, false><<<dim3(DIN / 128, LROWS / 128, 1), 256, SM_NN>>>(
        zrec, EE, 0, 0, decW, DIN, 0, 0, dec_b,
        out, DIN, 0, 0, EE, 1.0f, 1);

    // 8) x_pred = tile of last chunk of x_rec
    pred_kernel<<<(BB * 192 * 64 / 4) / 256, 256>>>(out, out + (long long)BB * 384 * 64);
}

// round 8
// speedup vs baseline: 1.5532x; 1.5532x over previous
#include <cuda_runtime.h>
#include <cuda_fp16.h>
#include <math.h>

#define BB   512
#define FREQ 8
#define EE   1024
#define HH   8
#define HD   128
#define DIN  3072
#define LROWS 4096
#define SEQ  512
#define NH   64
#define LDQKV (3 * EE * FREQ)   // 24576 halfs between consecutive l (fixed n)

// fp16 tensors
__device__ __half g_xh[LROWS * DIN];
__device__ __half g_zh[LROWS * EE];
__device__ __half g_qkvh[LROWS * 3 * EE];
__device__ __half g_ph[NH * SEQ * SEQ];
__device__ __half g_vt[NH * HD * SEQ];
__device__ __half g_aoh[LROWS * EE];
__device__ __half g_zrech[LROWS * EE];
__device__ __half g_encWTh[EE * DIN];     // enc_W^T  [1024][3072]
__device__ __half g_inprojh[3 * EE * EE]; // [3072][1024] (already NT)
__device__ __half g_outh[EE * EE];        // [1024][1024] (already NT)
__device__ __half g_decWTh[DIN * EE];     // dec_W^T  [3072][1024]
// fp32
__device__ float g_scores[NH * SEQ * SEQ];

// ---------------- helpers ----------------
__device__ __forceinline__ unsigned smem_u32(const void* p) {
    unsigned a;
    asm("{ .reg .u64 t; cvta.to.shared.u64 t, %1; cvt.u32.u64 %0, t; }"
        : "=r"(a) : "l"(p));
    return a;
}
__device__ __forceinline__ void cp16(unsigned dst, const void* src) {
    asm volatile("cp.async.cg.shared.global [%0], [%1], 16;" :: "r"(dst), "l"(src));
}
__device__ __forceinline__ void mma_f16(float c[4], const unsigned a[4], const unsigned b[2]) {
    asm volatile(
        "mma.sync.aligned.m16n8k16.row.col.f32.f16.f16.f32 "
        "{%0,%1,%2,%3}, {%4,%5,%6,%7}, {%8,%9}, {%0,%1,%2,%3};\n"
        : "+f"(c[0]), "+f"(c[1]), "+f"(c[2]), "+f"(c[3])
        : "r"(a[0]), "r"(a[1]), "r"(a[2]), "r"(a[3]), "r"(b[0]), "r"(b[1]));
}

// ---------------- fp16 NT GEMM ----------------
// C = alpha * A @ B^T + bias.  A:[M,K] half, B:[N,K] half, both row-major.
// 128x128 CTA tile, K-step 32, 8 warps of 64x32, double-buffered cp.async.
// OUTH=1 -> C half, OUTH=0 -> C float.
#define HS 40          // smem row stride in halfs (32 k + 8 pad) -> conflict-free

template<int OUTH>
__global__ __launch_bounds__(256, 1)
void gemm_h(const __half* __restrict__ A, long long lda, long long sA1, long long sA2,
            const __half* __restrict__ B, long long ldb, long long sB1, long long sB2,
            const float* __restrict__ bias,
            void* __restrict__ Cv, long long ldc, long long sC1, long long sC2,
            int K, float alpha, int bdiv)
{
    __shared__ __half As[2][128 * HS];
    __shared__ __half Bs[2][128 * HS];

    const int bz = blockIdx.z;
    const int n_b = bz / bdiv, h_b = bz % bdiv;
    A += n_b * sA1 + h_b * sA2;
    B += n_b * sB1 + h_b * sB2;
    const long long coff = (long long)n_b * sC1 + (long long)h_b * sC2;
    __half* Ch = (__half*)Cv + coff;
    float*  Cf = (float*)Cv + coff;

    const int rowBase = blockIdx.y * 128;
    const int colBase = blockIdx.x * 128;
    const int tid  = threadIdx.x;
    const int wid  = tid >> 5;
    const int lane = tid & 31;
    const int warpM = wid >> 2;      // 0..1
    const int warpN = wid & 3;       // 0..3
    const int gid = lane >> 2;       // 0..7
    const int tig = lane & 3;        // 0..3

    // copy mapping: thread -> (row = tid>>2, slot = tid&3) and row+64
    const int crow = tid >> 2;
    const int cslot = (tid & 3) * 8;            // halfs
    const __half* aSrc = A + (long long)(rowBase + crow) * lda + cslot;
    const __half* bSrc = B + (long long)(colBase + crow) * ldb + cslot;
    const long long aHalfRow = 64LL * lda;
    const long long bHalfRow = 64LL * ldb;
    const unsigned aD0 = smem_u32(&As[0][crow * HS + cslot]);
    const unsigned aD1 = smem_u32(&As[1][crow * HS + cslot]);
    const unsigned bD0 = smem_u32(&Bs[0][crow * HS + cslot]);
    const unsigned bD1 = smem_u32(&Bs[1][crow * HS + cslot]);
    const unsigned ROW64 = 64u * HS * 2u;       // bytes

    float acc[4][4][4];
#pragma unroll
    for (int i = 0; i < 4; i++)
#pragma unroll
        for (int j = 0; j < 4; j++)
#pragma unroll
            for (int r = 0; r < 4; r++) acc[i][j][r] = 0.0f;

    const int KT = K >> 5;

    auto issue = [&](int kt) {
        const int k0 = kt << 5;
        const unsigned ad = (kt & 1) ? aD1 : aD0;
        const unsigned bd = (kt & 1) ? bD1 : bD0;
        cp16(ad,         aSrc + k0);
        cp16(ad + ROW64, aSrc + aHalfRow + k0);
        cp16(bd,         bSrc + k0);
        cp16(bd + ROW64, bSrc + bHalfRow + k0);
        asm volatile("cp.async.commit_group;" ::: "memory");
    };

    issue(0);

    for (int kt = 0; kt < KT; kt++) {
        if (kt + 1 < KT) {
            issue(kt + 1);
            asm volatile("cp.async.wait_group 1;" ::: "memory");
        } else {
            asm volatile("cp.async.wait_group 0;" ::: "memory");
        }
        __syncthreads();

        const __half* as = As[kt & 1];
        const __half* bs = Bs[kt & 1];

#pragma unroll
        for (int ks = 0; ks < 32; ks += 16) {
            unsigned afr[4][4];
#pragma unroll
            for (int mt = 0; mt < 4; mt++) {
                const int r = warpM * 64 + mt * 16 + gid;
                const __half* pa = &as[r * HS + ks + 2 * tig];
                afr[mt][0] = *(const unsigned*)pa;
                afr[mt][1] = *(const unsigned*)(pa + 8 * HS);
                afr[mt][2] = *(const unsigned*)(pa + 8);
                afr[mt][3] = *(const unsigned*)(pa + 8 * HS + 8);
            }
            unsigned bfr[4][2];
#pragma unroll
            for (int nt = 0; nt < 4; nt++) {
                const int n = warpN * 32 + nt * 8 + gid;
                const __half* pb = &bs[n * HS + ks + 2 * tig];
                bfr[nt][0] = *(const unsigned*)pb;
                bfr[nt][1] = *(const unsigned*)(pb + 8);
            }
#pragma unroll
            for (int mt = 0; mt < 4; mt++)
#pragma unroll
                for (int nt = 0; nt < 4; nt++)
                    mma_f16(acc[mt][nt], afr[mt], bfr[nt]);
        }
        __syncthreads();
    }

    // epilogue
#pragma unroll
    for (int mt = 0; mt < 4; mt++) {
        const int r0 = rowBase + warpM * 64 + mt * 16 + gid;
#pragma unroll
        for (int nt = 0; nt < 4; nt++) {
            const int c0 = colBase + warpN * 32 + nt * 8 + tig * 2;
            float b0 = 0.0f, b1 = 0.0f;
            if (bias) { b0 = bias[c0]; b1 = bias[c0 + 1]; }
            const float v00 = acc[mt][nt][0] * alpha + b0;
            const float v01 = acc[mt][nt][1] * alpha + b1;
            const float v10 = acc[mt][nt][2] * alpha + b0;
            const float v11 = acc[mt][nt][3] * alpha + b1;
            if (OUTH) {
                *(__half2*)(Ch + (long long)r0 * ldc + c0)       = __floats2half2_rn(v00, v01);
                *(__half2*)(Ch + (long long)(r0 + 8) * ldc + c0) = __floats2half2_rn(v10, v11);
            } else {
                *(float2*)(Cf + (long long)r0 * ldc + c0)       = make_float2(v00, v01);
                *(float2*)(Cf + (long long)(r0 + 8) * ldc + c0) = make_float2(v10, v11);
            }
        }
    }
}

// ---------------- conversion / transpose kernels ----------------
__global__ __launch_bounds__(256)
void conv_h(const float4* __restrict__ in, __half2* __restrict__ out, int n4)
{
    for (int i = blockIdx.x * blockDim.x + threadIdx.x; i < n4;
         i += gridDim.x * blockDim.x) {
        const float4 v = in[i];
        out[2 * i]     = __floats2half2_rn(v.x, v.y);
        out[2 * i + 1] = __floats2half2_rn(v.z, v.w);
    }
}

// in f32 [R][Ccols] -> out half [Ccols][R]
__global__ __launch_bounds__(256)
void transpose_h(const float* __restrict__ in, __half* __restrict__ out,
                 int R, int Ccols)
{
    __shared__ float t[32][33];
    const int c0 = blockIdx.x * 32, r0 = blockIdx.y * 32;
    const int x = threadIdx.x & 31, y = threadIdx.x >> 5;   // 32 x 8
#pragma unroll
    for (int i = 0; i < 32; i += 8)
        t[y + i][x] = in[(long long)(r0 + y + i) * Ccols + c0 + x];
    __syncthreads();
#pragma unroll
    for (int i = 0; i < 32; i += 8)
        out[(long long)(c0 + y + i) * R + r0 + x] = __float2half_rn(t[x][y + i]);
}

// V[m][d] (strided in qkv_h) -> vt[bz][d][m]
__global__ __launch_bounds__(256)
void transpose_v(const __half* __restrict__ qkv, __half* __restrict__ vt)
{
    const int bz = blockIdx.z;
    const int n = bz >> 3, h = bz & 7;
    const __half* src = qkv + 2 * EE + n * 3 * EE + h * HD;
    const int m0 = blockIdx.x * 32, d0 = blockIdx.y * 32;
    __shared__ __half t[32][33];
    const int x = threadIdx.x & 31, y = threadIdx.x >> 5;
#pragma unroll
    for (int i = 0; i < 32; i += 8)
        t[y + i][x] = src[(long long)(m0 + y + i) * LDQKV + d0 + x];
    __syncthreads();
#pragma unroll
    for (int i = 0; i < 32; i += 8)
        vt[((long long)bz * HD + d0 + y + i) * SEQ + m0 + x] = t[x][y + i];
}

__global__ __launch_bounds__(256)
void softmax512(const float* __restrict__ S, __half* __restrict__ P)
{
    const float* p = S + (long long)blockIdx.x * 512;
    __half* q = P + (long long)blockIdx.x * 512;
    const int t = threadIdx.x;
    const float a = p[t];
    const float b = p[t + 256];

    float m = fmaxf(a, b);
#pragma unroll
    for (int o = 16; o; o >>= 1) m = fmaxf(m, __shfl_xor_sync(0xFFFFFFFFu, m, o));
    __shared__ float sm[8];
    if ((t & 31) == 0) sm[t >> 5] = m;
    __syncthreads();
    float mm = sm[0];
#pragma unroll
    for (int i = 1; i < 8; i++) mm = fmaxf(mm, sm[i]);

    const float e0 = __expf(a - mm);
    const float e1 = __expf(b - mm);
    float s = e0 + e1;
#pragma unroll
    for (int o = 16; o; o >>= 1) s += __shfl_xor_sync(0xFFFFFFFFu, s, o);
    __shared__ float ss[8];
    if ((t & 31) == 0) ss[t >> 5] = s;
    __syncthreads();
    float tot = 0.0f;
#pragma unroll
    for (int i = 0; i < 8; i++) tot += ss[i];
    const float inv = 1.0f / tot;
    q[t]       = __float2half_rn(e0 * inv);
    q[t + 256] = __float2half_rn(e1 * inv);
}

__global__ __launch_bounds__(256)
void pred_kernel(const float* __restrict__ xrec, float* __restrict__ xpred)
{
    const int idx = blockIdx.x * blockDim.x + threadIdx.x;
    const int c4 = idx & 15;
    const int t  = (idx >> 4) % 192;
    const int b  = idx / (16 * 192);
    const int s  = t % 48;
    const float4 v = *(const float4*)(xrec + (long long)b * 24576 + 7 * 3072 + s * 64 + c4 * 4);
    ((float4*)xpred)[idx] = v;
}

// ---------------- launch ----------------
extern "C" void kernel_launch(void* const* d_in, const int* in_sizes, int n_in,
                              void* d_out, int out_size)
{
    const float* x        = (const float*)d_in[0];
    const float* enc_W    = (const float*)d_in[1];
    const float* enc_b    = (const float*)d_in[2];
    const float* dec_W    = (const float*)d_in[3];
    const float* dec_b    = (const float*)d_in[4];
    const float* in_projW = (const float*)d_in[5];
    const float* in_projb = (const float*)d_in[6];
    const float* out_W    = (const float*)d_in[7];
    const float* out_b    = (const float*)d_in[8];
    float* out = (float*)d_out;

    __half *xh, *zh, *qkvh, *ph, *vt, *aoh, *zrech, *encWTh, *inprojh, *outh, *decWTh;
    float* scores;
    cudaGetSymbolAddress((void**)&xh,      g_xh);
    cudaGetSymbolAddress((void**)&zh,      g_zh);
    cudaGetSymbolAddress((void**)&qkvh,    g_qkvh);
    cudaGetSymbolAddress((void**)&ph,      g_ph);
    cudaGetSymbolAddress((void**)&vt,      g_vt);
    cudaGetSymbolAddress((void**)&aoh,     g_aoh);
    cudaGetSymbolAddress((void**)&zrech,   g_zrech);
    cudaGetSymbolAddress((void**)&encWTh,  g_encWTh);
    cudaGetSymbolAddress((void**)&inprojh, g_inprojh);
    cudaGetSymbolAddress((void**)&outh,    g_outh);
    cudaGetSymbolAddress((void**)&decWTh,  g_decWTh);
    cudaGetSymbolAddress((void**)&scores,  g_scores);

    const float att_scale = 1.0f / sqrtf((float)HD);

    // 0) convert / transpose weights + input (grid-stride, capped grids)
    conv_h<<<2048, 256>>>((const float4*)x, (__half2*)xh, LROWS * DIN / 4);
    conv_h<<<1024, 256>>>((const float4*)in_projW, (__half2*)inprojh, 3 * EE * EE / 4);
    conv_h<<<512, 256>>>((const float4*)out_W, (__half2*)outh, EE * EE / 4);
    transpose_h<<<dim3(EE / 32, DIN / 32), 256>>>(enc_W, encWTh, DIN, EE);
    transpose_h<<<dim3(DIN / 32, EE / 32), 256>>>(dec_W, decWTh, EE, DIN);

    // 1) z = x @ enc_W + enc_b              (4096x1024x3072) -> fp16
    gemm_h<1><<<dim3(EE / 128, LROWS / 128, 1), 256>>>(
        xh, DIN, 0, 0, encWTh, DIN, 0, 0, enc_b,
        zh, EE, 0, 0, DIN, 1.0f, 1);

    // 2) qkv = z @ in_proj_W^T + b          (4096x3072x1024) -> fp16
    gemm_h<1><<<dim3(3 * EE / 128, LROWS / 128, 1), 256>>>(
        zh, EE, 0, 0, inprojh, EE, 0, 0, in_projb,
        qkvh, 3 * EE, 0, 0, EE, 1.0f, 1);

    // 2b) V transpose (only needs qkv; off softmax's critical path)
    transpose_v<<<dim3(SEQ / 32, HD / 32, NH), 256>>>(qkvh, vt);

    // 3) scores = alpha * Q @ K^T           (64 x 512x512x128) -> fp32
    gemm_h<0><<<dim3(SEQ / 128, SEQ / 128, NH), 256>>>(
        qkvh,      LDQKV, 3 * EE, HD,
        qkvh + EE, LDQKV, 3 * EE, HD,
        nullptr,
        scores, SEQ, (long long)HH * SEQ * SEQ, (long long)SEQ * SEQ,
        HD, att_scale, HH);

    // 4) softmax -> P fp16
    softmax512<<<NH * SEQ, 256>>>(scores, ph);

    // 5) attn_o = P @ Vt^T into (L,N,E)     (64 x 512x128x512) -> fp16
    gemm_h<1><<<dim3(HD / 128, SEQ / 128, NH), 256>>>(
        ph, SEQ, (long long)HH * SEQ * SEQ, (long long)SEQ * SEQ,
        vt, SEQ, (long long)HH * HD * SEQ, (long long)HD * SEQ,
        nullptr,
        aoh, (long long)FREQ * EE, EE, HD,
        SEQ, 1.0f, HH);

    // 6) z_rec = attn_o @ out_W^T + b       (4096x1024x1024) -> fp16
    gemm_h<1><<<dim3(EE / 128, LROWS / 128, 1), 256>>>(
        aoh, EE, 0, 0, outh, EE, 0, 0, out_b,
        zrech, EE, 0, 0, EE, 1.0f, 1);

    // 7) x_rec = z_rec @ dec_W + b -> d_out (4096x3072x1024) -> fp32
    gemm_h<0><<<dim3(DIN / 128, LROWS / 128, 1), 256>>>(
        zrech, EE, 0, 0, decWTh, EE, 0, 0, dec_b,
        out, DIN, 0, 0, EE, 1.0f, 1);

    // 8) x_pred = tile of last chunk of x_rec
    pred_kernel<<<(BB * 192 * 64 / 4) / 256, 256>>>(out, out + (long long)BB * 384 * 64);
}

// round 9
// speedup vs baseline: 1.5581x; 1.0031x over previous
#include <cuda_runtime.h>
#include <cuda_fp16.h>
#include <math.h>

#define BB   512
#define FREQ 8
#define EE   1024
#define HH   8
#define HD   128
#define DIN  3072
#define LROWS 4096
#define SEQ  512
#define NH   64
#define LDQKV (3 * EE * FREQ)   // 24576 halfs between consecutive l (fixed n)

// fp16 tensors
__device__ __half g_xh[LROWS * DIN];
__device__ __half g_zh[LROWS * EE];
__device__ __half g_qkvh[LROWS * 3 * EE];
__device__ __half g_ph[NH * SEQ * SEQ];    // scores, then P (in-place softmax)
__device__ __half g_vt[NH * HD * SEQ];
__device__ __half g_aoh[LROWS * EE];
__device__ __half g_zrech[LROWS * EE];
__device__ __half g_encWTh[EE * DIN];      // enc_W^T  [1024][3072]
__device__ __half g_inprojh[3 * EE * EE];  // [3072][1024] (already NT)
__device__ __half g_outh[EE * EE];         // [1024][1024] (already NT)
__device__ __half g_decWTh[DIN * EE];      // dec_W^T  [3072][1024]

// ---------------- helpers ----------------
__device__ __forceinline__ unsigned smem_u32(const void* p) {
    unsigned a;
    asm("{ .reg .u64 t; cvta.to.shared.u64 t, %1; cvt.u32.u64 %0, t; }"
        : "=r"(a) : "l"(p));
    return a;
}
__device__ __forceinline__ void cp16(unsigned dst, const void* src) {
    asm volatile("cp.async.cg.shared.global [%0], [%1], 16;" :: "r"(dst), "l"(src));
}
__device__ __forceinline__ void mma_f16(float c[4], const unsigned a[4], const unsigned b[2]) {
    asm volatile(
        "mma.sync.aligned.m16n8k16.row.col.f32.f16.f16.f32 "
        "{%0,%1,%2,%3}, {%4,%5,%6,%7}, {%8,%9}, {%0,%1,%2,%3};\n"
        : "+f"(c[0]), "+f"(c[1]), "+f"(c[2]), "+f"(c[3])
        : "r"(a[0]), "r"(a[1]), "r"(a[2]), "r"(a[3]), "r"(b[0]), "r"(b[1]));
}
__device__ __forceinline__ void ldm_x4(unsigned* r, unsigned addr) {
    asm volatile("ldmatrix.sync.aligned.m8n8.x4.shared.b16 {%0,%1,%2,%3}, [%4];"
        : "=r"(r[0]), "=r"(r[1]), "=r"(r[2]), "=r"(r[3]) : "r"(addr));
}
__device__ __forceinline__ void ldm_x2(unsigned* r, unsigned addr) {
    asm volatile("ldmatrix.sync.aligned.m8n8.x2.shared.b16 {%0,%1}, [%2];"
        : "=r"(r[0]), "=r"(r[1]) : "r"(addr));
}

// ---------------- fp16 NT GEMM ----------------
// C = alpha * A @ B^T + bias.  A:[M,K] half, B:[N,K] half, both row-major.
// 128x128 CTA tile, K-step 32, 8 warps of 64x32, double-buffered cp.async,
// fragments via ldmatrix.  OUTH=1 -> C half, OUTH=0 -> C float.
#define HS 40          // smem row stride in halfs (32 k + 8 pad)

template<int OUTH>
__global__ __launch_bounds__(256, 1)
void gemm_h(const __half* __restrict__ A, long long lda, long long sA1, long long sA2,
            const __half* __restrict__ B, long long ldb, long long sB1, long long sB2,
            const float* __restrict__ bias,
            void* __restrict__ Cv, long long ldc, long long sC1, long long sC2,
            int K, float alpha, int bdiv)
{
    __shared__ __half As[2][128 * HS];
    __shared__ __half Bs[2][128 * HS];

    const int bz = blockIdx.z;
    const int n_b = bz / bdiv, h_b = bz % bdiv;
    A += n_b * sA1 + h_b * sA2;
    B += n_b * sB1 + h_b * sB2;
    const long long coff = (long long)n_b * sC1 + (long long)h_b * sC2;
    __half* Ch = (__half*)Cv + coff;
    float*  Cf = (float*)Cv + coff;

    const int rowBase = blockIdx.y * 128;
    const int colBase = blockIdx.x * 128;
    const int tid  = threadIdx.x;
    const int wid  = tid >> 5;
    const int lane = tid & 31;
    const int warpM = wid >> 2;      // 0..1
    const int warpN = wid & 3;       // 0..3
    const int gid = lane >> 2;       // 0..7
    const int tig = lane & 3;        // 0..3

    // copy mapping: thread -> (row = tid>>2, slot = tid&3) and row+64
    const int crow = tid >> 2;
    const int cslot = (tid & 3) * 8;            // halfs
    const __half* aSrc = A + (long long)(rowBase + crow) * lda + cslot;
    const __half* bSrc = B + (long long)(colBase + crow) * ldb + cslot;
    const long long aHalfRow = 64LL * lda;
    const long long bHalfRow = 64LL * ldb;
    const unsigned aD0 = smem_u32(&As[0][crow * HS + cslot]);
    const unsigned aD1 = smem_u32(&As[1][crow * HS + cslot]);
    const unsigned bD0 = smem_u32(&Bs[0][crow * HS + cslot]);
    const unsigned bD1 = smem_u32(&Bs[1][crow * HS + cslot]);
    const unsigned ROW64 = 64u * HS * 2u;       // bytes

    // ldmatrix per-lane address components
    const int aRow = lane & 15;                  // rows 0..15 within 16-row frag
    const int aK   = (lane >> 4) << 3;           // 0 or 8 (k offset)
    const int bRow = lane & 7;
    const int bK   = ((lane >> 3) & 1) << 3;
    // base (bytes) of this lane's A-frag row for mt=0, ks=0, buffer 0/1:
    const unsigned aL0 = smem_u32(&As[0][(warpM * 64 + aRow) * HS + aK]);
    const unsigned aL1 = smem_u32(&As[1][(warpM * 64 + aRow) * HS + aK]);
    const unsigned bL0 = smem_u32(&Bs[0][(warpN * 32 + bRow) * HS + bK]);
    const unsigned bL1 = smem_u32(&Bs[1][(warpN * 32 + bRow) * HS + bK]);

    float acc[4][4][4];
#pragma unroll
    for (int i = 0; i < 4; i++)
#pragma unroll
        for (int j = 0; j < 4; j++)
#pragma unroll
            for (int r = 0; r < 4; r++) acc[i][j][r] = 0.0f;

    const int KT = K >> 5;

    auto issue = [&](int kt) {
        const int k0 = kt << 5;
        const unsigned ad = (kt & 1) ? aD1 : aD0;
        const unsigned bd = (kt & 1) ? bD1 : bD0;
        cp16(ad,         aSrc + k0);
        cp16(ad + ROW64, aSrc + aHalfRow + k0);
        cp16(bd,         bSrc + k0);
        cp16(bd + ROW64, bSrc + bHalfRow + k0);
        asm volatile("cp.async.commit_group;" ::: "memory");
    };

    issue(0);

    for (int kt = 0; kt < KT; kt++) {
        if (kt + 1 < KT) {
            issue(kt + 1);
            asm volatile("cp.async.wait_group 1;" ::: "memory");
        } else {
            asm volatile("cp.async.wait_group 0;" ::: "memory");
        }
        __syncthreads();

        const unsigned aL = (kt & 1) ? aL1 : aL0;
        const unsigned bL = (kt & 1) ? bL1 : bL0;

#pragma unroll
        for (int ks = 0; ks < 32; ks += 16) {
            unsigned afr[4][4];
#pragma unroll
            for (int mt = 0; mt < 4; mt++)
                ldm_x4(afr[mt], aL + (mt * 16 * HS + ks) * 2);
            unsigned bfr[4][2];
#pragma unroll
            for (int nt = 0; nt < 4; nt++)
                ldm_x2(bfr[nt], bL + (nt * 8 * HS + ks) * 2);
#pragma unroll
            for (int mt = 0; mt < 4; mt++)
#pragma unroll
                for (int nt = 0; nt < 4; nt++)
                    mma_f16(acc[mt][nt], afr[mt], bfr[nt]);
        }
        __syncthreads();
    }

    // epilogue
#pragma unroll
    for (int mt = 0; mt < 4; mt++) {
        const int r0 = rowBase + warpM * 64 + mt * 16 + gid;
#pragma unroll
        for (int nt = 0; nt < 4; nt++) {
            const int c0 = colBase + warpN * 32 + nt * 8 + tig * 2;
            float b0 = 0.0f, b1 = 0.0f;
            if (bias) { b0 = bias[c0]; b1 = bias[c0 + 1]; }
            const float v00 = acc[mt][nt][0] * alpha + b0;
            const float v01 = acc[mt][nt][1] * alpha + b1;
            const float v10 = acc[mt][nt][2] * alpha + b0;
            const float v11 = acc[mt][nt][3] * alpha + b1;
            if (OUTH) {
                *(__half2*)(Ch + (long long)r0 * ldc + c0)       = __floats2half2_rn(v00, v01);
                *(__half2*)(Ch + (long long)(r0 + 8) * ldc + c0) = __floats2half2_rn(v10, v11);
            } else {
                *(float2*)(Cf + (long long)r0 * ldc + c0)       = make_float2(v00, v01);
                *(float2*)(Cf + (long long)(r0 + 8) * ldc + c0) = make_float2(v10, v11);
            }
        }
    }
}

// ---------------- conversion / transpose kernels ----------------
__global__ __launch_bounds__(256)
void conv_h(const float4* __restrict__ in, __half2* __restrict__ out, int n4)
{
    for (int i = blockIdx.x * blockDim.x + threadIdx.x; i < n4;
         i += gridDim.x * blockDim.x) {
        const float4 v = in[i];
        out[2 * i]     = __floats2half2_rn(v.x, v.y);
        out[2 * i + 1] = __floats2half2_rn(v.z, v.w);
    }
}

// in f32 [R][Ccols] -> out half [Ccols][R]
__global__ __launch_bounds__(256)
void transpose_h(const float* __restrict__ in, __half* __restrict__ out,
                 int R, int Ccols)
{
    __shared__ float t[32][33];
    const int c0 = blockIdx.x * 32, r0 = blockIdx.y * 32;
    const int x = threadIdx.x & 31, y = threadIdx.x >> 5;   // 32 x 8
#pragma unroll
    for (int i = 0; i < 32; i += 8)
        t[y + i][x] = in[(long long)(r0 + y + i) * Ccols + c0 + x];
    __syncthreads();
#pragma unroll
    for (int i = 0; i < 32; i += 8)
        out[(long long)(c0 + y + i) * R + r0 + x] = __float2half_rn(t[x][y + i]);
}

// V[m][d] (strided in qkv_h) -> vt[bz][d][m]
__global__ __launch_bounds__(256)
void transpose_v(const __half* __restrict__ qkv, __half* __restrict__ vt)
{
    const int bz = blockIdx.z;
    const int n = bz >> 3, h = bz & 7;
    const __half* src = qkv + 2 * EE + n * 3 * EE + h * HD;
    const int m0 = blockIdx.x * 32, d0 = blockIdx.y * 32;
    __shared__ __half t[32][33];
    const int x = threadIdx.x & 31, y = threadIdx.x >> 5;
#pragma unroll
    for (int i = 0; i < 32; i += 8)
        t[y + i][x] = src[(long long)(m0 + y + i) * LDQKV + d0 + x];
    __syncthreads();
#pragma unroll
    for (int i = 0; i < 32; i += 8)
        vt[((long long)bz * HD + d0 + y + i) * SEQ + m0 + x] = t[x][y + i];
}

// in-place softmax over rows of 512 halfs
__global__ __launch_bounds__(256)
void softmax512h(__half* __restrict__ P)
{
    __half* p = P + (long long)blockIdx.x * 512;
    const int t = threadIdx.x;
    const float a = __half2float(p[t]);
    const float b = __half2float(p[t + 256]);

    float m = fmaxf(a, b);
#pragma unroll
    for (int o = 16; o; o >>= 1) m = fmaxf(m, __shfl_xor_sync(0xFFFFFFFFu, m, o));
    __shared__ float sm[8];
    if ((t & 31) == 0) sm[t >> 5] = m;
    __syncthreads();
    float mm = sm[0];
#pragma unroll
    for (int i = 1; i < 8; i++) mm = fmaxf(mm, sm[i]);

    const float e0 = __expf(a - mm);
    const float e1 = __expf(b - mm);
    float s = e0 + e1;
#pragma unroll
    for (int o = 16; o; o >>= 1) s += __shfl_xor_sync(0xFFFFFFFFu, s, o);
    __shared__ float ss[8];
    if ((t & 31) == 0) ss[t >> 5] = s;
    __syncthreads();
    float tot = 0.0f;
#pragma unroll
    for (int i = 0; i < 8; i++) tot += ss[i];
    const float inv = 1.0f / tot;
    p[t]       = __float2half_rn(e0 * inv);
    p[t + 256] = __float2half_rn(e1 * inv);
}

__global__ __launch_bounds__(256)
void pred_kernel(const float* __restrict__ xrec, float* __restrict__ xpred)
{
    const int idx = blockIdx.x * blockDim.x + threadIdx.x;
    const int c4 = idx & 15;
    const int t  = (idx >> 4) % 192;
    const int b  = idx / (16 * 192);
    const int s  = t % 48;
    const float4 v = *(const float4*)(xrec + (long long)b * 24576 + 7 * 3072 + s * 64 + c4 * 4);
    ((float4*)xpred)[idx] = v;
}

// ---------------- launch ----------------
extern "C" void kernel_launch(void* const* d_in, const int* in_sizes, int n_in,
                              void* d_out, int out_size)
{
    const float* x        = (const float*)d_in[0];
    const float* enc_W    = (const float*)d_in[1];
    const float* enc_b    = (const float*)d_in[2];
    const float* dec_W    = (const float*)d_in[3];
    const float* dec_b    = (const float*)d_in[4];
    const float* in_projW = (const float*)d_in[5];
    const float* in_projb = (const float*)d_in[6];
    const float* out_W    = (const float*)d_in[7];
    const float* out_b    = (const float*)d_in[8];
    float* out = (float*)d_out;

    __half *xh, *zh, *qkvh, *ph, *vt, *aoh, *zrech, *encWTh, *inprojh, *outh, *decWTh;
    cudaGetSymbolAddress((void**)&xh,      g_xh);
    cudaGetSymbolAddress((void**)&zh,      g_zh);
    cudaGetSymbolAddress((void**)&qkvh,    g_qkvh);
    cudaGetSymbolAddress((void**)&ph,      g_ph);
    cudaGetSymbolAddress((void**)&vt,      g_vt);
    cudaGetSymbolAddress((void**)&aoh,     g_aoh);
    cudaGetSymbolAddress((void**)&zrech,   g_zrech);
    cudaGetSymbolAddress((void**)&encWTh,  g_encWTh);
    cudaGetSymbolAddress((void**)&inprojh, g_inprojh);
    cudaGetSymbolAddress((void**)&outh,    g_outh);
    cudaGetSymbolAddress((void**)&decWTh,  g_decWTh);

    const float att_scale = 1.0f / sqrtf((float)HD);

    // 0) convert / transpose weights + input
    conv_h<<<2048, 256>>>((const float4*)x, (__half2*)xh, LROWS * DIN / 4);
    conv_h<<<1024, 256>>>((const float4*)in_projW, (__half2*)inprojh, 3 * EE * EE / 4);
    conv_h<<<512, 256>>>((const float4*)out_W, (__half2*)outh, EE * EE / 4);
    transpose_h<<<dim3(EE / 32, DIN / 32), 256>>>(enc_W, encWTh, DIN, EE);
    transpose_h<<<dim3(DIN / 32, EE / 32), 256>>>(dec_W, decWTh, EE, DIN);

    // 1) z = x @ enc_W + enc_b              (4096x1024x3072) -> fp16
    gemm_h<1><<<dim3(EE / 128, LROWS / 128, 1), 256>>>(
        xh, DIN, 0, 0, encWTh, DIN, 0, 0, enc_b,
        zh, EE, 0, 0, DIN, 1.0f, 1);

    // 2) qkv = z @ in_proj_W^T + b          (4096x3072x1024) -> fp16
    gemm_h<1><<<dim3(3 * EE / 128, LROWS / 128, 1), 256>>>(
        zh, EE, 0, 0, inprojh, EE, 0, 0, in_projb,
        qkvh, 3 * EE, 0, 0, EE, 1.0f, 1);

    // 2b) V transpose (only needs qkv)
    transpose_v<<<dim3(SEQ / 32, HD / 32, NH), 256>>>(qkvh, vt);

    // 3) scores = alpha * Q @ K^T           (64 x 512x512x128) -> fp16 (into ph)
    gemm_h<1><<<dim3(SEQ / 128, SEQ / 128, NH), 256>>>(
        qkvh,      LDQKV, 3 * EE, HD,
        qkvh + EE, LDQKV, 3 * EE, HD,
        nullptr,
        ph, SEQ, (long long)HH * SEQ * SEQ, (long long)SEQ * SEQ,
        HD, att_scale, HH);

    // 4) softmax in place on ph
    softmax512h<<<NH * SEQ, 256>>>(ph);

    // 5) attn_o = P @ Vt^T into (L,N,E)     (64 x 512x128x512) -> fp16
    gemm_h<1><<<dim3(HD / 128, SEQ / 128, NH), 256>>>(
        ph, SEQ, (long long)HH * SEQ * SEQ, (long long)SEQ * SEQ,
        vt, SEQ, (long long)HH * HD * SEQ, (long long)HD * SEQ,
        nullptr,
        aoh, (long long)FREQ * EE, EE, HD,
        SEQ, 1.0f, HH);

    // 6) z_rec = attn_o @ out_W^T + b       (4096x1024x1024) -> fp16
    gemm_h<1><<<dim3(EE / 128, LROWS / 128, 1), 256>>>(
        aoh, EE, 0, 0, outh, EE, 0, 0, out_b,
        zrech, EE, 0, 0, EE, 1.0f, 1);

    // 7) x_rec = z_rec @ dec_W + b -> d_out (4096x3072x1024) -> fp32
    gemm_h<0><<<dim3(DIN / 128, LROWS / 128, 1), 256>>>(
        zrech, EE, 0, 0, decWTh, EE, 0, 0, dec_b,
        out, DIN, 0, 0, EE, 1.0f, 1);

    // 8) x_pred = tile of last chunk of x_rec
    pred_kernel<<<(BB * 192 * 64 / 4) / 256, 256>>>(out, out + (long long)BB * 384 * 64);
}

// round 10
// speedup vs baseline: 1.7033x; 1.0932x over previous
#include <cuda_runtime.h>
#include <cuda_fp16.h>
#include <math.h>

#define BB   512
#define FREQ 8
#define EE   1024
#define HH   8
#define HD   128
#define DIN  3072
#define LROWS 4096
#define SEQ  512
#define NH   64
#define LDQKV (3 * EE * FREQ)   // 24576 halfs between consecutive l (fixed n)

// fp16 tensors
__device__ __half g_xh[LROWS * DIN];
__device__ __half g_zh[LROWS * EE];
__device__ __half g_qkvh[LROWS * 3 * EE];
__device__ __half g_ph[NH * SEQ * SEQ];    // scores then P (in-place softmax)
__device__ __half g_aoh[LROWS * EE];
__device__ __half g_zrech[LROWS * EE];
__device__ __half g_encWh[DIN * EE];       // enc_W [3072][1024] (NN operand)
__device__ __half g_inprojh[3 * EE * EE];  // [3072][1024] (NT operand)
__device__ __half g_outh[EE * EE];         // [1024][1024] (NT operand)
__device__ __half g_decWh[EE * DIN];       // dec_W [1024][3072] (NN operand)

// ---------------- helpers ----------------
__device__ __forceinline__ unsigned smem_u32(const void* p) {
    unsigned a;
    asm("{ .reg .u64 t; cvta.to.shared.u64 t, %1; cvt.u32.u64 %0, t; }"
        : "=r"(a) : "l"(p));
    return a;
}
__device__ __forceinline__ void cp16(unsigned dst, const void* src) {
    asm volatile("cp.async.cg.shared.global [%0], [%1], 16;" :: "r"(dst), "l"(src));
}
__device__ __forceinline__ void mma_f16(float c[4], const unsigned a[4], const unsigned b[2]) {
    asm volatile(
        "mma.sync.aligned.m16n8k16.row.col.f32.f16.f16.f32 "
        "{%0,%1,%2,%3}, {%4,%5,%6,%7}, {%8,%9}, {%0,%1,%2,%3};\n"
        : "+f"(c[0]), "+f"(c[1]), "+f"(c[2]), "+f"(c[3])
        : "r"(a[0]), "r"(a[1]), "r"(a[2]), "r"(a[3]), "r"(b[0]), "r"(b[1]));
}
__device__ __forceinline__ void ldm_x4(unsigned* r, unsigned addr) {
    asm volatile("ldmatrix.sync.aligned.m8n8.x4.shared.b16 {%0,%1,%2,%3}, [%4];"
        : "=r"(r[0]), "=r"(r[1]), "=r"(r[2]), "=r"(r[3]) : "r"(addr));
}
__device__ __forceinline__ void ldm_x2(unsigned* r, unsigned addr) {
    asm volatile("ldmatrix.sync.aligned.m8n8.x2.shared.b16 {%0,%1}, [%2];"
        : "=r"(r[0]), "=r"(r[1]) : "r"(addr));
}
__device__ __forceinline__ void ldm_x2t(unsigned* r, unsigned addr) {
    asm volatile("ldmatrix.sync.aligned.m8n8.x2.trans.shared.b16 {%0,%1}, [%2];"
        : "=r"(r[0]), "=r"(r[1]) : "r"(addr));
}

// ---------------- fp16 GEMM ----------------
// C = alpha * A @ op(B) + bias.  A:[M,K] half row-major.
// BNN=0: B [N,K] row-major (NT).  BNN=1: B [K,N] row-major (NN, trans-ldmatrix).
// 128x128 CTA tile, K-step 32, 8 warps of 64x32, double-buffered cp.async.
// OUTH=1 -> C half, OUTH=0 -> C float.
#define HS 40           // A (and NT-B) smem row stride in halfs
#define BP 136          // NN-B smem row pitch in halfs (128 + 8 pad -> 272 B)

template<int OUTH, int BNN>
__global__ __launch_bounds__(256, 1)
void gemm_h(const __half* __restrict__ A, long long lda, long long sA1, long long sA2,
            const __half* __restrict__ B, long long ldb, long long sB1, long long sB2,
            const float* __restrict__ bias,
            void* __restrict__ Cv, long long ldc, long long sC1, long long sC2,
            int K, float alpha, int bdiv)
{
    __shared__ __half As[2][128 * HS];
    __shared__ __half Bs[2][BNN ? (32 * BP) : (128 * HS)];

    const int bz = blockIdx.z;
    const int n_b = bz / bdiv, h_b = bz % bdiv;
    A += n_b * sA1 + h_b * sA2;
    B += n_b * sB1 + h_b * sB2;
    const long long coff = (long long)n_b * sC1 + (long long)h_b * sC2;
    __half* Ch = (__half*)Cv + coff;
    float*  Cf = (float*)Cv + coff;

    const int rowBase = blockIdx.y * 128;
    const int colBase = blockIdx.x * 128;
    const int tid  = threadIdx.x;
    const int wid  = tid >> 5;
    const int lane = tid & 31;
    const int warpM = wid >> 2;      // 0..1
    const int warpN = wid & 3;       // 0..3
    const int gid = lane >> 2;       // 0..7
    const int tig = lane & 3;        // 0..3

    // ---- A copy mapping (both variants) ----
    const int crow = tid >> 2;
    const int cslot = (tid & 3) * 8;            // halfs
    const __half* aSrc = A + (long long)(rowBase + crow) * lda + cslot;
    const long long aHalfRow = 64LL * lda;
    const unsigned aD0 = smem_u32(&As[0][crow * HS + cslot]);
    const unsigned aD1 = smem_u32(&As[1][crow * HS + cslot]);
    const unsigned ROW64 = 64u * HS * 2u;       // bytes

    // ---- B copy mapping ----
    const __half* bSrc;
    unsigned bD0, bD1;
    long long bHalfRow = 0;
    if (BNN) {
        const int brow = tid >> 3;              // k-row 0..31
        const int bc   = (tid & 7) * 8;         // halfs 0..56
        bSrc = B + (long long)brow * ldb + colBase + bc;   // + second half at +64
        bD0 = smem_u32(&Bs[0][brow * BP + bc]);
        bD1 = smem_u32(&Bs[1][brow * BP + bc]);
    } else {
        bSrc = B + (long long)(colBase + crow) * ldb + cslot;
        bHalfRow = 64LL * ldb;
        bD0 = smem_u32(&Bs[0][crow * HS + cslot]);
        bD1 = smem_u32(&Bs[1][crow * HS + cslot]);
    }

    // ---- ldmatrix lane addresses ----
    const int aRow = lane & 15;
    const int aK   = (lane >> 4) << 3;
    const unsigned aL0 = smem_u32(&As[0][(warpM * 64 + aRow) * HS + aK]);
    const unsigned aL1 = smem_u32(&As[1][(warpM * 64 + aRow) * HS + aK]);
    unsigned bL0, bL1;
    if (BNN) {
        const int kR = (lane & 7) | (((lane >> 3) & 1) << 3);   // 0..15
        bL0 = smem_u32(&Bs[0][kR * BP + warpN * 32]);
        bL1 = smem_u32(&Bs[1][kR * BP + warpN * 32]);
    } else {
        const int bRow = lane & 7;
        const int bK   = ((lane >> 3) & 1) << 3;
        bL0 = smem_u32(&Bs[0][(warpN * 32 + bRow) * HS + bK]);
        bL1 = smem_u32(&Bs[1][(warpN * 32 + bRow) * HS + bK]);
    }

    float acc[4][4][4];
#pragma unroll
    for (int i = 0; i < 4; i++)
#pragma unroll
        for (int j = 0; j < 4; j++)
#pragma unroll
            for (int r = 0; r < 4; r++) acc[i][j][r] = 0.0f;

    const int KT = K >> 5;

    auto issue = [&](int kt) {
        const int k0 = kt << 5;
        const unsigned ad = (kt & 1) ? aD1 : aD0;
        const unsigned bd = (kt & 1) ? bD1 : bD0;
        cp16(ad,         aSrc + k0);
        cp16(ad + ROW64, aSrc + aHalfRow + k0);
        if (BNN) {
            const __half* bs = bSrc + (long long)k0 * ldb;
            cp16(bd,       bs);
            cp16(bd + 128, bs + 64);     // second 128B half of the 256B row
        } else {
            cp16(bd,         bSrc + k0);
            cp16(bd + ROW64, bSrc + bHalfRow + k0);
        }
        asm volatile("cp.async.commit_group;" ::: "memory");
    };

    issue(0);

    for (int kt = 0; kt < KT; kt++) {
        if (kt + 1 < KT) {
            issue(kt + 1);
            asm volatile("cp.async.wait_group 1;" ::: "memory");
        } else {
            asm volatile("cp.async.wait_group 0;" ::: "memory");
        }
        __syncthreads();

        const unsigned aL = (kt & 1) ? aL1 : aL0;
        const unsigned bL = (kt & 1) ? bL1 : bL0;

#pragma unroll
        for (int ks = 0; ks < 32; ks += 16) {
            unsigned afr[4][4];
#pragma unroll
            for (int mt = 0; mt < 4; mt++)
                ldm_x4(afr[mt], aL + (mt * 16 * HS + ks) * 2);
            unsigned bfr[4][2];
#pragma unroll
            for (int nt = 0; nt < 4; nt++) {
                if (BNN) ldm_x2t(bfr[nt], bL + (ks * BP + nt * 8) * 2);
                else     ldm_x2 (bfr[nt], bL + (nt * 8 * HS + ks) * 2);
            }
#pragma unroll
            for (int mt = 0; mt < 4; mt++)
#pragma unroll
                for (int nt = 0; nt < 4; nt++)
                    mma_f16(acc[mt][nt], afr[mt], bfr[nt]);
        }
        __syncthreads();
    }

    // epilogue
#pragma unroll
    for (int mt = 0; mt < 4; mt++) {
        const int r0 = rowBase + warpM * 64 + mt * 16 + gid;
#pragma unroll
        for (int nt = 0; nt < 4; nt++) {
            const int c0 = colBase + warpN * 32 + nt * 8 + tig * 2;
            float b0 = 0.0f, b1 = 0.0f;
            if (bias) { b0 = bias[c0]; b1 = bias[c0 + 1]; }
            const float v00 = acc[mt][nt][0] * alpha + b0;
            const float v01 = acc[mt][nt][1] * alpha + b1;
            const float v10 = acc[mt][nt][2] * alpha + b0;
            const float v11 = acc[mt][nt][3] * alpha + b1;
            if (OUTH) {
                *(__half2*)(Ch + (long long)r0 * ldc + c0)       = __floats2half2_rn(v00, v01);
                *(__half2*)(Ch + (long long)(r0 + 8) * ldc + c0) = __floats2half2_rn(v10, v11);
            } else {
                *(float2*)(Cf + (long long)r0 * ldc + c0)       = make_float2(v00, v01);
                *(float2*)(Cf + (long long)(r0 + 8) * ldc + c0) = make_float2(v10, v11);
            }
        }
    }
}

// ---------------- fused prep: fp32 -> fp16 for 5 segments ----------------
__global__ __launch_bounds__(256)
void prep_all(const float4* s0, __half2* d0, int n0,
              const float4* s1, __half2* d1, int n1,
              const float4* s2, __half2* d2, int n2,
              const float4* s3, __half2* d3, int n3,
              const float4* s4, __half2* d4, int n4tot)
{
    const int total = n0 + n1 + n2 + n3 + n4tot;
    for (int i = blockIdx.x * blockDim.x + threadIdx.x; i < total;
         i += gridDim.x * blockDim.x) {
        const float4* s; __half2* d; int j = i;
        if (j < n0)                { s = s0; d = d0; }
        else if ((j -= n0) < n1)   { s = s1; d = d1; }
        else if ((j -= n1) < n2)   { s = s2; d = d2; }
        else if ((j -= n2) < n3)   { s = s3; d = d3; }
        else { j -= n3;              s = s4; d = d4; }
        const float4 v = s[j];
        d[2 * j]     = __floats2half2_rn(v.x, v.y);
        d[2 * j + 1] = __floats2half2_rn(v.z, v.w);
    }
}

// ---------------- warp-per-row softmax, rows of 512 halfs, in place ----------------
__global__ __launch_bounds__(256)
void softmax_warp(__half* __restrict__ P)
{
    const int row  = blockIdx.x * 8 + (threadIdx.x >> 5);
    const int lane = threadIdx.x & 31;
    uint4* p = (uint4*)(P + (long long)row * 512);   // 64 uint4 per row
    uint4 u0 = p[lane * 2];
    uint4 u1 = p[lane * 2 + 1];

    __half2* h0 = (__half2*)&u0;
    __half2* h1 = (__half2*)&u1;
    float v[16];
#pragma unroll
    for (int i = 0; i < 4; i++) {
        const float2 a = __half22float2(h0[i]);
        const float2 b = __half22float2(h1[i]);
        v[2 * i] = a.x; v[2 * i + 1] = a.y;
        v[8 + 2 * i] = b.x; v[8 + 2 * i + 1] = b.y;
    }
    float m = v[0];
#pragma unroll
    for (int i = 1; i < 16; i++) m = fmaxf(m, v[i]);
#pragma unroll
    for (int o = 16; o; o >>= 1) m = fmaxf(m, __shfl_xor_sync(0xFFFFFFFFu, m, o));
    float s = 0.0f;
#pragma unroll
    for (int i = 0; i < 16; i++) { v[i] = __expf(v[i] - m); s += v[i]; }
#pragma unroll
    for (int o = 16; o; o >>= 1) s += __shfl_xor_sync(0xFFFFFFFFu, s, o);
    const float inv = 1.0f / s;
#pragma unroll
    for (int i = 0; i < 4; i++) {
        h0[i] = __floats2half2_rn(v[2 * i] * inv, v[2 * i + 1] * inv);
        h1[i] = __floats2half2_rn(v[8 + 2 * i] * inv, v[8 + 2 * i + 1] * inv);
    }
    p[lane * 2]     = u0;
    p[lane * 2 + 1] = u1;
}

__global__ __launch_bounds__(256)
void pred_kernel(const float* __restrict__ xrec, float* __restrict__ xpred)
{
    const int idx = blockIdx.x * blockDim.x + threadIdx.x;
    const int c4 = idx & 15;
    const int t  = (idx >> 4) % 192;
    const int b  = idx / (16 * 192);
    const int s  = t % 48;
    const float4 v = *(const float4*)(xrec + (long long)b * 24576 + 7 * 3072 + s * 64 + c4 * 4);
    ((float4*)xpred)[idx] = v;
}

// ---------------- launch ----------------
extern "C" void kernel_launch(void* const* d_in, const int* in_sizes, int n_in,
                              void* d_out, int out_size)
{
    const float* x        = (const float*)d_in[0];
    const float* enc_W    = (const float*)d_in[1];
    const float* enc_b    = (const float*)d_in[2];
    const float* dec_W    = (const float*)d_in[3];
    const float* dec_b    = (const float*)d_in[4];
    const float* in_projW = (const float*)d_in[5];
    const float* in_projb = (const float*)d_in[6];
    const float* out_W    = (const float*)d_in[7];
    const float* out_b    = (const float*)d_in[8];
    float* out = (float*)d_out;

    __half *xh, *zh, *qkvh, *ph, *aoh, *zrech, *encWh, *inprojh, *outh, *decWh;
    cudaGetSymbolAddress((void**)&xh,      g_xh);
    cudaGetSymbolAddress((void**)&zh,      g_zh);
    cudaGetSymbolAddress((void**)&qkvh,    g_qkvh);
    cudaGetSymbolAddress((void**)&ph,      g_ph);
    cudaGetSymbolAddress((void**)&aoh,     g_aoh);
    cudaGetSymbolAddress((void**)&zrech,   g_zrech);
    cudaGetSymbolAddress((void**)&encWh,   g_encWh);
    cudaGetSymbolAddress((void**)&inprojh, g_inprojh);
    cudaGetSymbolAddress((void**)&outh,    g_outh);
    cudaGetSymbolAddress((void**)&decWh,   g_decWh);

    const float att_scale = 1.0f / sqrtf((float)HD);

    // 0) one fused convert pass (x, enc_W, in_proj_W, out_W, dec_W -> fp16, layouts kept)
    prep_all<<<2048, 256>>>(
        (const float4*)x,        (__half2*)xh,      LROWS * DIN / 4,
        (const float4*)enc_W,    (__half2*)encWh,   DIN * EE / 4,
        (const float4*)in_projW, (__half2*)inprojh, 3 * EE * EE / 4,
        (const float4*)out_W,    (__half2*)outh,    EE * EE / 4,
        (const float4*)dec_W,    (__half2*)decWh,   EE * DIN / 4);

    // 1) z = x @ enc_W + enc_b              (NN, 4096x1024x3072) -> fp16
    gemm_h<1, 1><<<dim3(EE / 128, LROWS / 128, 1), 256>>>(
        xh, DIN, 0, 0, encWh, EE, 0, 0, enc_b,
        zh, EE, 0, 0, DIN, 1.0f, 1);

    // 2) qkv = z @ in_proj_W^T + b          (NT, 4096x3072x1024) -> fp16
    gemm_h<1, 0><<<dim3(3 * EE / 128, LROWS / 128, 1), 256>>>(
        zh, EE, 0, 0, inprojh, EE, 0, 0, in_projb,
        qkvh, 3 * EE, 0, 0, EE, 1.0f, 1);

    // 3) scores = alpha * Q @ K^T           (NT batched, 64 x 512x512x128) -> fp16
    gemm_h<1, 0><<<dim3(SEQ / 128, SEQ / 128, NH), 256>>>(
        qkvh,      LDQKV, 3 * EE, HD,
        qkvh + EE, LDQKV, 3 * EE, HD,
        nullptr,
        ph, SEQ, (long long)HH * SEQ * SEQ, (long long)SEQ * SEQ,
        HD, att_scale, HH);

    // 4) softmax in place (warp per row)
    softmax_warp<<<NH * SEQ / 8, 256>>>(ph);

    // 5) attn_o = P @ V into (L,N,E)        (NN batched, V read in place from qkv)
    gemm_h<1, 1><<<dim3(HD / 128, SEQ / 128, NH), 256>>>(
        ph, SEQ, (long long)HH * SEQ * SEQ, (long long)SEQ * SEQ,
        qkvh + 2 * EE, LDQKV, 3 * EE, HD,
        nullptr,
        aoh, (long long)FREQ * EE, EE, HD,
        SEQ, 1.0f, HH);

    // 6) z_rec = attn_o @ out_W^T + b       (NT, 4096x1024x1024) -> fp16
    gemm_h<1, 0><<<dim3(EE / 128, LROWS / 128, 1), 256>>>(
        aoh, EE, 0, 0, outh, EE, 0, 0, out_b,
        zrech, EE, 0, 0, EE, 1.0f, 1);

    // 7) x_rec = z_rec @ dec_W + b -> d_out (NN, 4096x3072x1024) -> fp32
    gemm_h<0, 1><<<dim3(DIN / 128, LROWS / 128, 1), 256>>>(
        zrech, EE, 0, 0, decWh, DIN, 0, 0, dec_b,
        out, DIN, 0, 0, EE, 1.0f, 1);

    // 8) x_pred = tile of last chunk of x_rec
    pred_kernel<<<(BB * 192 * 64 / 4) / 256, 256>>>(out, out + (long long)BB * 384 * 64);
}